// round 9
// baseline (speedup 1.0000x reference)
#include <cuda_runtime.h>
#include <cuda_bf16.h>
#include <cstdint>

// OHEM smooth-L1 loss. y_pred,y_true: [64, 262144] fp32 -> scalar fp32.
//  memset : zero scratch (~130 KB).
//  pass_a : sweep; stage "interesting" (p,t) pairs (pos OR |p|>=1.5625) in
//           private smem slots; phase 2 -> pos stats + counts-only 512-bin
//           hist (global RED) + big-neg a-sum. Warp shuffle reduce + smem
//           combine -> 4 atomics/block.
//  pass_e : ONE block x 1024 thr. 128 KB smem holds all 64 row histograms;
//           each warp finishes 2 rows fully warp-locally (two-stage shfl
//           select + linear neg-sum reconstruction). Rare exact fallback.
//           Same block emits the final scalar. No tickets/fences/atomics.

static constexpr int B = 64;
static constexpr int N = 256 * 256 * 4;        // 262144
static constexpr int NBINS = 512;
static constexpr int SHIFT = 15;               // (key-CUT)>>15 -> 512 bins, 2 octaves
static constexpr unsigned CUT_BITS = 0x3FC80000u;   // 1.5625f
static constexpr float   CUTF = 1.5625f;

static constexpr int TPB = 256;
static constexpr int VEC = 4;
static constexpr int ITERS = 4;
static constexpr int EPB = TPB * VEC * ITERS;   // 4096
static constexpr int BPR = N / EPB;             // 64

static constexpr int TPE = 1024;

struct Zeroed {
    unsigned hist[B][NBINS];   // 128 KB
    unsigned pos_cnt[B];
    unsigned big_cnt[B];
    double   pos_sum[B];
    double   big_suma[B];
};
__device__ Zeroed g_z;

__device__ __forceinline__ float fsl1(float a) {
    float u = fminf(a, 1.0f);
    return fmaf(u, fmaf(0.5f, u, -1.0f), a);   // exact smooth_l1, branch-free
}
__device__ __forceinline__ float bin_center(int b) {
    return __uint_as_float(CUT_BITS + ((unsigned)b << SHIFT) + (1u << (SHIFT - 1)));
}

// valid in thread 0; internally barriered; all threads must call
__device__ double block_reduce_double(double v) {
    __shared__ double sh[32];
    int lane = threadIdx.x & 31, w = threadIdx.x >> 5;
    #pragma unroll
    for (int o = 16; o; o >>= 1) v += __shfl_down_sync(0xffffffffu, v, o);
    __syncthreads();
    if (lane == 0) sh[w] = v;
    __syncthreads();
    double r = 0.0;
    if (w == 0) {
        int nw = (blockDim.x + 31) >> 5;
        r = (lane < nw) ? sh[lane] : 0.0;
        #pragma unroll
        for (int o = 16; o; o >>= 1) r += __shfl_down_sync(0xffffffffu, r, o);
    }
    __syncthreads();
    return r;
}

// Warp-local suffix select over a 512-bin hist. All 32 lanes active.
// Returns in every lane: b*, c = count(bins > b*), with c < keff <= c + h[b*].
__device__ void warp_select512(const unsigned* h, unsigned keff,
                               int& ob, unsigned& oc) {
    const int lane = threadIdx.x & 31;
    // stage 1: 16 bins per lane
    unsigned cs = 0;
    #pragma unroll
    for (int j = 0; j < 16; j++) cs += h[lane * 16 + j];
    unsigned v = cs;
    #pragma unroll
    for (int off = 1; off < 32; off <<= 1) {
        unsigned g = __shfl_down_sync(0xffffffffu, v, off);
        if (lane + off < 32) v += g;
    }
    unsigned vnext = __shfl_down_sync(0xffffffffu, v, 1);
    if (lane == 31) vnext = 0u;
    bool hit = (v >= keff) && (vnext < keff);
    unsigned hb = __ballot_sync(0xffffffffu, hit);
    int c = __ffs(hb) - 1;
    unsigned S = __shfl_sync(0xffffffffu, vnext, c);
    // stage 2: 16 bins of chunk c, lanes 0..15
    unsigned hv = (lane < 16) ? h[c * 16 + lane] : 0u;
    unsigned w = hv;
    #pragma unroll
    for (int off = 1; off < 16; off <<= 1) {
        unsigned gg = __shfl_down_sync(0xffffffffu, w, off);
        if (lane + off < 16) w += gg;
    }
    unsigned wnext = __shfl_down_sync(0xffffffffu, w, 1);
    if (lane >= 15) wnext = 0u;
    bool hit2 = (lane < 16) && (S + w >= keff) && (S + wnext < keff);
    unsigned hb2 = __ballot_sync(0xffffffffu, hit2);
    int l = __ffs(hb2) - 1;
    ob = c * 16 + l;
    oc = S + __shfl_sync(0xffffffffu, wnext, l);
}

// ---------------- Pass A: data sweep -----------------------------------------
__global__ void __launch_bounds__(TPB) pass_a(const float* __restrict__ yp,
                                              const float* __restrict__ yt) {
    __shared__ float2 sbuf[TPB][17];            // 16 slots + pad; 34.8 KB
    __shared__ float rs_ps[8], rs_bs[8];
    __shared__ int   rs_pc[8], rs_bc[8];
    const int r = blockIdx.y;
    const int tid = threadIdx.x;
    const unsigned lane = tid & 31u;
    const int w = tid >> 5;
    const size_t base = (size_t)r * N + (size_t)blockIdx.x * EPB;
    int cnt = 0;

    // phase 1: filter + stage (1 FFMA + 1 FSETP + predicated STS.64 per elem)
    #pragma unroll
    for (int it = 0; it < ITERS; it++) {
        size_t idx = base + (size_t)it * (TPB * VEC) + (size_t)tid * VEC;
        float4 p = *reinterpret_cast<const float4*>(yp + idx);
        float4 t = *reinterpret_cast<const float4*>(yt + idx);
        float pv[4] = {p.x, p.y, p.z, p.w};
        float tv[4] = {t.x, t.y, t.z, t.w};
        #pragma unroll
        for (int j = 0; j < 4; j++) {
            // t!=0 -> w huge; t==0 -> w=|p|.  interesting <=> w >= CUTF
            float wv = fmaf(fabsf(tv[j]), 1e38f, fabsf(pv[j]));
            if (wv >= CUTF) { sbuf[tid][cnt] = make_float2(pv[j], tv[j]); cnt++; }
        }
    }

    // phase 2: process staged entries (private slots; no sync needed)
    float psum = 0.f, bsum = 0.f; int pc = 0, bc = 0;
    for (int c = 0; c < cnt; c++) {
        float2 e = sbuf[tid][c];
        if (e.y != 0.f) {                        // positive
            psum += fsl1(fabsf(e.x - e.y));
            pc++;
        } else {                                 // big negative (|p| >= 1.5625)
            float a = fabsf(e.x);
            unsigned bin = (__float_as_uint(a) - CUT_BITS) >> SHIFT;
            bin = min(bin, (unsigned)(NBINS - 1));
            atomicAdd(&g_z.hist[r][bin], 1u);    // fire-and-forget RED
            bsum += a; bc++;
        }
    }

    // per-warp shuffle reduce -> smem -> thread 0 -> 4 atomics (1 barrier)
    #pragma unroll
    for (int o = 16; o; o >>= 1) {
        psum += __shfl_down_sync(0xffffffffu, psum, o);
        bsum += __shfl_down_sync(0xffffffffu, bsum, o);
        pc   += __shfl_down_sync(0xffffffffu, pc, o);
        bc   += __shfl_down_sync(0xffffffffu, bc, o);
    }
    if (lane == 0) { rs_ps[w] = psum; rs_bs[w] = bsum; rs_pc[w] = pc; rs_bc[w] = bc; }
    __syncthreads();
    if (tid == 0) {
        double PS = 0.0, BS = 0.0; int PC = 0, BC = 0;
        #pragma unroll
        for (int i = 0; i < 8; i++) {
            PS += (double)rs_ps[i]; BS += (double)rs_bs[i];
            PC += rs_pc[i]; BC += rs_bc[i];
        }
        if (PC) { atomicAdd(&g_z.pos_sum[r], PS); atomicAdd(&g_z.pos_cnt[r], (unsigned)PC); }
        if (BC) { atomicAdd(&g_z.big_suma[r], BS); atomicAdd(&g_z.big_cnt[r], (unsigned)BC); }
    }
}

// ---------------- Pass E: single block finishes everything -------------------
extern __shared__ unsigned dyn_s[];             // B * NBINS u32 = 128 KB

__global__ void __launch_bounds__(TPE) pass_e(const float* __restrict__ yp,
                                              const float* __restrict__ yt,
                                              float* __restrict__ out) {
    const int tid = threadIdx.x;
    unsigned (*s_h)[NBINS] = reinterpret_cast<unsigned(*)[NBINS]>(dyn_s);
    __shared__ double s_negr[B];
    __shared__ double s_kd[B];
    __shared__ int    s_fb[B];
    __shared__ int s_b; __shared__ unsigned s_c;

    // cooperative load: 128 KB = 8192 uint4 over 1024 threads
    {
        const uint4* src = reinterpret_cast<const uint4*>(&g_z.hist[0][0]);
        uint4* dst = reinterpret_cast<uint4*>(dyn_s);
        #pragma unroll
        for (int i = 0; i < B * NBINS / 4 / TPE; i++)
            dst[i * TPE + tid] = src[i * TPE + tid];
    }
    __syncthreads();

    const int w = tid >> 5, lane = tid & 31;
    // each warp finishes 2 rows, fully warp-local
    #pragma unroll
    for (int rr = 0; rr < 2; rr++) {
        const int r = w * 2 + rr;
        const unsigned pcr = g_z.pos_cnt[r];
        const unsigned bcr = g_z.big_cnt[r];
        const double   bsa = g_z.big_suma[r];
        unsigned k = 2u * pcr; if (k > (unsigned)(N - 1)) k = (unsigned)(N - 1);
        const unsigned keff = (k < bcr) ? k : bcr;
        double negr = 0.0;
        if (keff > 0) {
            int b1; unsigned cab;
            warp_select512(s_h[r], keff, b1, cab);
            double acc = 0.0;                   // a-sum over unselected bigs
            for (int b = lane; b < b1; b += 32)
                acc += (double)s_h[r][b] * (double)bin_center(b);
            #pragma unroll
            for (int o = 16; o; o >>= 1) acc += __shfl_down_sync(0xffffffffu, acc, o);
            if (lane == 0) {
                unsigned part_unsel = s_h[r][b1] - (keff - cab);
                acc += (double)part_unsel * (double)bin_center(b1);
                negr = bsa - acc - 0.5 * (double)keff;
            }
        }
        if (lane == 0) { s_negr[r] = negr; s_kd[r] = (double)k; s_fb[r] = (bcr < k); }
    }
    __syncthreads();

    // rare fallback: block-wide per flagged row (top k-bc among below-cut negs)
    for (int r = 0; r < B; r++) {
        if (!s_fb[r]) continue;
        unsigned* f_h = s_h[0];                 // reuse (all selects already done)
        float*    f_f = reinterpret_cast<float*>(s_h[1]);
        for (int i = tid; i < NBINS; i += TPE) { f_h[i] = 0u; f_f[i] = 0.f; }
        __syncthreads();
        const size_t rb = (size_t)r * N;
        for (int i = tid; i < N; i += TPE) {
            float p = yp[rb + i], t = yt[rb + i];
            if (t == 0.f) {
                float a = fabsf(p);
                if (a < CUTF) {
                    unsigned bin = __float_as_uint(a) >> 21;
                    bin = min(bin, (unsigned)(NBINS - 1));
                    atomicAdd(&f_h[bin], 1u);
                    atomicAdd(&f_f[bin], fsl1(a));
                }
            }
        }
        __syncthreads();
        double dt = 0.0;
        for (int i = tid; i < NBINS; i += TPE) dt += (double)f_h[i];
        dt = block_reduce_double(dt);
        if (tid == 0) s_c = (unsigned)(dt + 0.5);
        __syncthreads();
        unsigned tot = s_c;
        unsigned k2 = (unsigned)(s_kd[r] + 0.5);
        unsigned bcr = g_z.big_cnt[r];
        unsigned kc = k2 - bcr; if (kc > tot) kc = tot;
        __syncthreads();
        if (kc > 0) {
            if (tid < 32) {
                int b1; unsigned cab;
                warp_select512(f_h, kc, b1, cab);
                if (lane == 0) { s_b = b1; s_c = cab; }
            }
            __syncthreads();
            const int b1 = s_b; const unsigned cab = s_c;
            double ext = 0.0;
            for (int b = b1 + 1 + tid; b < NBINS; b += TPE) ext += (double)f_f[b];
            ext = block_reduce_double(ext);
            if (tid == 0) {
                unsigned part = kc - cab;
                if (f_h[b1]) ext += (double)part * ((double)f_f[b1] / (double)f_h[b1]);
                s_negr[r] += ext;
            }
            __syncthreads();
        }
    }

    // final scalar (same block; no global handshake needed)
    double ns  = (tid < B) ? s_negr[tid] : 0.0;
    double nc  = (tid < B) ? s_kd[tid] : 0.0;
    double ps  = (tid < B) ? g_z.pos_sum[tid] : 0.0;
    double pcs = (tid < B) ? (double)g_z.pos_cnt[tid] : 0.0;
    ns = block_reduce_double(ns);
    nc = block_reduce_double(nc);
    ps = block_reduce_double(ps);
    pcs = block_reduce_double(pcs);
    if (tid == 0) {
        double pos_loss = (pcs > 0.0) ? ps / pcs : 0.0;
        double neg_loss = (nc > 0.0) ? ns / nc : 0.0;
        out[0] = (float)(2.0 * pos_loss + neg_loss);
    }
}

// ---------------- launch ------------------------------------------------------
extern "C" void kernel_launch(void* const* d_in, const int* in_sizes, int n_in,
                              void* d_out, int out_size) {
    const float* yp = (const float*)d_in[0];
    const float* yt = (const float*)d_in[1];
    float* out = (float*)d_out;

    static bool attr_set = false;
    if (!attr_set) {
        cudaFuncSetAttribute(pass_e, cudaFuncAttributeMaxDynamicSharedMemorySize,
                             B * NBINS * (int)sizeof(unsigned));
        attr_set = true;
    }

    void* zp = nullptr;
    cudaGetSymbolAddress(&zp, g_z);
    cudaMemsetAsync(zp, 0, sizeof(Zeroed));

    pass_a<<<dim3(BPR, B), TPB>>>(yp, yt);
    pass_e<<<1, TPE, B * NBINS * sizeof(unsigned)>>>(yp, yt, out);
}

// round 10
// speedup vs baseline: 1.4818x; 1.4818x over previous
#include <cuda_runtime.h>
#include <cuda_bf16.h>
#include <cstdint>

// OHEM smooth-L1 loss. y_pred,y_true: [64, 262144] fp32 -> scalar fp32.
//  memset : zero scratch (~513 KB).
//  pass_a : sweep; stage "interesting" (p,t) pairs (pos OR |p|>=1.5625) in
//           private smem slots; phase 2 -> pos stats + counts-only 2048-bin
//           hist (global RED) + big-neg a-sum. Warp shuffle reduce + smem
//           combine -> 4 atomics/block.
//  pass_e : 16 blocks x 1024 thr, 4 rows/block, one WARP per row: top-k
//           select + linear neg-sum reconstruction warp-locally over smem
//           histograms (parallel 512KB load across 16 SMs). Rare exact
//           fallback. 16-block ticket -> final scalar.

static constexpr int B = 64;
static constexpr int N = 256 * 256 * 4;        // 262144
static constexpr int NBINS = 2048;
static constexpr int SHIFT = 13;               // (key-CUT)>>13 -> 2048 bins, 2 octaves
static constexpr unsigned CUT_BITS = 0x3FC80000u;   // 1.5625f
static constexpr float   CUTF = 1.5625f;

static constexpr int TPB = 256;
static constexpr int VEC = 4;
static constexpr int ITERS = 4;
static constexpr int EPB = TPB * VEC * ITERS;   // 4096
static constexpr int BPR = N / EPB;             // 64

static constexpr int RPB_E = 4;                 // rows per pass_e block
static constexpr int GRID_E = B / RPB_E;        // 16
static constexpr int TPE = 1024;

struct Zeroed {
    unsigned hist[B][NBINS];
    unsigned pos_cnt[B];
    unsigned big_cnt[B];
    double   pos_sum[B];
    double   big_suma[B];
    double   ns, nc;
    unsigned ticket;
};
__device__ Zeroed g_z;         // ~513 KB memset per launch

__device__ __forceinline__ float fsl1(float a) {
    float u = fminf(a, 1.0f);
    return fmaf(u, fmaf(0.5f, u, -1.0f), a);   // exact smooth_l1, branch-free
}
__device__ __forceinline__ float bin_center(int b) {
    return __uint_as_float(CUT_BITS + ((unsigned)b << SHIFT) + (1u << (SHIFT - 1)));
}

// valid in thread 0; internally barriered; all threads must call
__device__ double block_reduce_double(double v) {
    __shared__ double sh[32];
    int lane = threadIdx.x & 31, w = threadIdx.x >> 5;
    #pragma unroll
    for (int o = 16; o; o >>= 1) v += __shfl_down_sync(0xffffffffu, v, o);
    __syncthreads();
    if (lane == 0) sh[w] = v;
    __syncthreads();
    double r = 0.0;
    if (w == 0) {
        int nw = (blockDim.x + 31) >> 5;
        r = (lane < nw) ? sh[lane] : 0.0;
        #pragma unroll
        for (int o = 16; o; o >>= 1) r += __shfl_down_sync(0xffffffffu, r, o);
    }
    __syncthreads();
    return r;
}

// Warp-local suffix select over a 2048-bin hist. All 32 lanes active.
// Returns in every lane: b*, c = count(bins > b*), c < keff <= c + h[b*].
__device__ void warp_select2(const unsigned* h, unsigned keff,
                             int& ob, unsigned& oc) {
    const int lane = threadIdx.x & 31;
    const int chunk = NBINS >> 5;              // 64
    unsigned cs = 0;
    #pragma unroll 8
    for (int j = 0; j < chunk; j++) cs += h[lane * chunk + j];
    unsigned v = cs;
    #pragma unroll
    for (int off = 1; off < 32; off <<= 1) {
        unsigned g = __shfl_down_sync(0xffffffffu, v, off);
        if (lane + off < 32) v += g;
    }
    unsigned vnext = __shfl_down_sync(0xffffffffu, v, 1);
    if (lane == 31) vnext = 0u;
    bool hit = (v >= keff) && (vnext < keff);
    unsigned hb = __ballot_sync(0xffffffffu, hit);
    int c = __ffs(hb) - 1;
    unsigned S = __shfl_sync(0xffffffffu, vnext, c);
    ob = 0; oc = 0;
    #pragma unroll
    for (int g = (chunk >> 5) - 1; g >= 0; g--) {
        unsigned hv = h[c * chunk + g * 32 + lane];
        unsigned w = hv;
        #pragma unroll
        for (int off = 1; off < 32; off <<= 1) {
            unsigned gg = __shfl_down_sync(0xffffffffu, w, off);
            if (lane + off < 32) w += gg;
        }
        unsigned wnext = __shfl_down_sync(0xffffffffu, w, 1);
        if (lane == 31) wnext = 0u;
        unsigned tot = __shfl_sync(0xffffffffu, w, 0);
        bool hit2 = (S + w >= keff) && (S + wnext < keff);
        unsigned hb2 = __ballot_sync(0xffffffffu, hit2);
        if (hb2) {
            int l = __ffs(hb2) - 1;
            unsigned wl = __shfl_sync(0xffffffffu, w, l);
            unsigned hl = __shfl_sync(0xffffffffu, hv, l);
            ob = c * chunk + g * 32 + l;
            oc = S + wl - hl;
            return;
        }
        S += tot;
    }
}

// ---------------- Pass A: data sweep (identical to round-8 config) -----------
__global__ void __launch_bounds__(TPB) pass_a(const float* __restrict__ yp,
                                              const float* __restrict__ yt) {
    __shared__ float2 sbuf[TPB][17];            // 16 slots + pad; 34.8 KB
    __shared__ float rs_ps[8], rs_bs[8];
    __shared__ int   rs_pc[8], rs_bc[8];
    const int r = blockIdx.y;
    const int tid = threadIdx.x;
    const unsigned lane = tid & 31u;
    const int w = tid >> 5;
    const size_t base = (size_t)r * N + (size_t)blockIdx.x * EPB;
    int cnt = 0;

    // phase 1: filter + stage (1 FFMA + 1 FSETP + predicated STS.64 per elem)
    #pragma unroll
    for (int it = 0; it < ITERS; it++) {
        size_t idx = base + (size_t)it * (TPB * VEC) + (size_t)tid * VEC;
        float4 p = *reinterpret_cast<const float4*>(yp + idx);
        float4 t = *reinterpret_cast<const float4*>(yt + idx);
        float pv[4] = {p.x, p.y, p.z, p.w};
        float tv[4] = {t.x, t.y, t.z, t.w};
        #pragma unroll
        for (int j = 0; j < 4; j++) {
            // t!=0 -> w huge; t==0 -> w=|p|.  interesting <=> w >= CUTF
            float wv = fmaf(fabsf(tv[j]), 1e38f, fabsf(pv[j]));
            if (wv >= CUTF) { sbuf[tid][cnt] = make_float2(pv[j], tv[j]); cnt++; }
        }
    }

    // phase 2: process staged entries (private slots; no sync needed)
    float psum = 0.f, bsum = 0.f; int pc = 0, bc = 0;
    for (int c = 0; c < cnt; c++) {
        float2 e = sbuf[tid][c];
        if (e.y != 0.f) {                        // positive
            psum += fsl1(fabsf(e.x - e.y));
            pc++;
        } else {                                 // big negative (|p| >= 1.5625)
            float a = fabsf(e.x);
            unsigned bin = (__float_as_uint(a) - CUT_BITS) >> SHIFT;
            bin = min(bin, (unsigned)(NBINS - 1));
            atomicAdd(&g_z.hist[r][bin], 1u);    // fire-and-forget RED
            bsum += a; bc++;
        }
    }

    // per-warp shuffle reduce -> smem -> thread 0 -> 4 atomics (1 barrier)
    #pragma unroll
    for (int o = 16; o; o >>= 1) {
        psum += __shfl_down_sync(0xffffffffu, psum, o);
        bsum += __shfl_down_sync(0xffffffffu, bsum, o);
        pc   += __shfl_down_sync(0xffffffffu, pc, o);
        bc   += __shfl_down_sync(0xffffffffu, bc, o);
    }
    if (lane == 0) { rs_ps[w] = psum; rs_bs[w] = bsum; rs_pc[w] = pc; rs_bc[w] = bc; }
    __syncthreads();
    if (tid == 0) {
        double PS = 0.0, BS = 0.0; int PC = 0, BC = 0;
        #pragma unroll
        for (int i = 0; i < 8; i++) {
            PS += (double)rs_ps[i]; BS += (double)rs_bs[i];
            PC += rs_pc[i]; BC += rs_bc[i];
        }
        if (PC) { atomicAdd(&g_z.pos_sum[r], PS); atomicAdd(&g_z.pos_cnt[r], (unsigned)PC); }
        if (BC) { atomicAdd(&g_z.big_suma[r], BS); atomicAdd(&g_z.big_cnt[r], (unsigned)BC); }
    }
}

// ---------------- Pass E: 16 blocks, 4 rows/block, one warp per row ----------
extern __shared__ unsigned dyn_s[];             // RPB_E * NBINS u32 = 32 KB

__global__ void __launch_bounds__(TPE) pass_e(const float* __restrict__ yp,
                                              const float* __restrict__ yt,
                                              float* __restrict__ out) {
    const int tid = threadIdx.x;
    const int row0 = blockIdx.x * RPB_E;
    unsigned (*s_h)[NBINS] = reinterpret_cast<unsigned(*)[NBINS]>(dyn_s);
    __shared__ double s_negr[RPB_E];
    __shared__ double s_kd[RPB_E];
    __shared__ int    s_fb[RPB_E];
    __shared__ int s_b; __shared__ unsigned s_c;
    __shared__ int s_last;

    // cooperative load of 4 row histograms (32 KB): 2 uint4 per thread
    {
        const uint4* src = reinterpret_cast<const uint4*>(&g_z.hist[row0][0]);
        uint4* dst = reinterpret_cast<uint4*>(dyn_s);
        #pragma unroll
        for (int i = 0; i < RPB_E * NBINS / 4 / TPE; i++)
            dst[i * TPE + tid] = src[i * TPE + tid];
    }
    __syncthreads();

    const int w = tid >> 5, lane = tid & 31;
    if (w < RPB_E) {
        const int r = row0 + w;
        const unsigned pcr = g_z.pos_cnt[r];
        const unsigned bcr = g_z.big_cnt[r];
        const double   bsa = g_z.big_suma[r];
        unsigned k = 2u * pcr; if (k > (unsigned)(N - 1)) k = (unsigned)(N - 1);
        const unsigned keff = (k < bcr) ? k : bcr;
        double negr = 0.0;
        if (keff > 0) {
            int b1; unsigned cab;
            warp_select2(s_h[w], keff, b1, cab);
            double acc = 0.0;                   // a-sum over unselected bigs
            for (int b = lane; b < b1; b += 32)
                acc += (double)s_h[w][b] * (double)bin_center(b);
            #pragma unroll
            for (int o = 16; o; o >>= 1) acc += __shfl_down_sync(0xffffffffu, acc, o);
            if (lane == 0) {
                unsigned part_unsel = s_h[w][b1] - (keff - cab);
                acc += (double)part_unsel * (double)bin_center(b1);
                negr = bsa - acc - 0.5 * (double)keff;
            }
        }
        if (lane == 0) { s_negr[w] = negr; s_kd[w] = (double)k; s_fb[w] = (bcr < k); }
    }
    __syncthreads();

    // rare fallback: whole block per flagged row (top k-bc among below-cut negs)
    for (int w2 = 0; w2 < RPB_E; w2++) {
        if (!s_fb[w2]) continue;
        const int r = row0 + w2;
        unsigned* f_h = s_h[0];
        float*    f_f = reinterpret_cast<float*>(s_h[1]);
        for (int i = tid; i < NBINS; i += TPE) { f_h[i] = 0u; f_f[i] = 0.f; }
        __syncthreads();
        const size_t rb = (size_t)r * N;
        for (int i = tid; i < N; i += TPE) {
            float p = yp[rb + i], t = yt[rb + i];
            if (t == 0.f) {
                float a = fabsf(p);
                if (a < CUTF) {
                    unsigned bin = __float_as_uint(a) >> 21;
                    bin = min(bin, (unsigned)(NBINS - 1));
                    atomicAdd(&f_h[bin], 1u);
                    atomicAdd(&f_f[bin], fsl1(a));
                }
            }
        }
        __syncthreads();
        double dt = 0.0;
        for (int i = tid; i < NBINS; i += TPE) dt += (double)f_h[i];
        dt = block_reduce_double(dt);
        if (tid == 0) s_c = (unsigned)(dt + 0.5);
        __syncthreads();
        unsigned tot = s_c;
        unsigned k2 = (unsigned)(s_kd[w2] + 0.5);
        unsigned bcr = g_z.big_cnt[r];
        unsigned kc = k2 - bcr; if (kc > tot) kc = tot;
        __syncthreads();
        if (kc > 0) {
            if (tid < 32) {
                int b1; unsigned cab;
                warp_select2(f_h, kc, b1, cab);
                if (lane == 0) { s_b = b1; s_c = cab; }
            }
            __syncthreads();
            const int b1 = s_b; const unsigned cab = s_c;
            double ext = 0.0;
            for (int b = b1 + 1 + tid; b < NBINS; b += TPE) ext += (double)f_f[b];
            ext = block_reduce_double(ext);
            if (tid == 0) {
                unsigned part = kc - cab;
                if (f_h[b1]) ext += (double)part * ((double)f_f[b1] / (double)f_h[b1]);
                s_negr[w2] += ext;
            }
            __syncthreads();
        }
    }

    if (tid < RPB_E) {
        atomicAdd(&g_z.ns, s_negr[tid]);
        atomicAdd(&g_z.nc, s_kd[tid]);
    }
    __threadfence();
    __syncthreads();
    if (tid == 0)
        s_last = (atomicAdd(&g_z.ticket, 1u) == (unsigned)(GRID_E - 1)) ? 1 : 0;
    __syncthreads();
    if (!s_last) return;

    // ---- final scalar (one block total) ----
    __threadfence();
    double ps  = (tid < B) ? g_z.pos_sum[tid] : 0.0;
    double pcs = (tid < B) ? (double)g_z.pos_cnt[tid] : 0.0;
    ps = block_reduce_double(ps);
    pcs = block_reduce_double(pcs);
    if (tid == 0) {
        double NS = g_z.ns, NC = g_z.nc;
        double pos_loss = (pcs > 0.0) ? ps / pcs : 0.0;
        double neg_loss = (NC > 0.0) ? NS / NC : 0.0;
        out[0] = (float)(2.0 * pos_loss + neg_loss);
    }
}

// ---------------- launch ------------------------------------------------------
extern "C" void kernel_launch(void* const* d_in, const int* in_sizes, int n_in,
                              void* d_out, int out_size) {
    const float* yp = (const float*)d_in[0];
    const float* yt = (const float*)d_in[1];
    float* out = (float*)d_out;

    static bool attr_set = false;
    if (!attr_set) {
        cudaFuncSetAttribute(pass_e, cudaFuncAttributeMaxDynamicSharedMemorySize,
                             RPB_E * NBINS * (int)sizeof(unsigned));
        attr_set = true;
    }

    void* zp = nullptr;
    cudaGetSymbolAddress(&zp, g_z);
    cudaMemsetAsync(zp, 0, sizeof(Zeroed));

    pass_a<<<dim3(BPR, B), TPB>>>(yp, yt);
    pass_e<<<GRID_E, TPE, RPB_E * NBINS * sizeof(unsigned)>>>(yp, yt, out);
}

// round 11
// speedup vs baseline: 1.5288x; 1.0317x over previous
#include <cuda_runtime.h>
#include <cuda_bf16.h>
#include <cstdint>

// OHEM smooth-L1 loss. y_pred,y_true: [64, 262144] fp32 -> scalar fp32.
//  memset : zero scratch (~513 KB).
//  pass_a : sweep with front-batched loads (MLP=8); stage "interesting" (p,t)
//           pairs (pos OR |p|>=1.5625) in private smem slots; phase 2 ->
//           pos stats + counts-only 2048-bin hist (global RED) + big-neg a-sum.
//  pass_e : 32 blocks x 1024 thr, 2 rows/block, one WARP per row: top-k select
//           + linear neg-sum reconstruction warp-locally over smem histograms.
//           Rare exact fallback. 32-block ticket -> final scalar.

static constexpr int B = 64;
static constexpr int N = 256 * 256 * 4;        // 262144
static constexpr int NBINS = 2048;
static constexpr int SHIFT = 13;               // (key-CUT)>>13 -> 2048 bins, 2 octaves
static constexpr unsigned CUT_BITS = 0x3FC80000u;   // 1.5625f
static constexpr float   CUTF = 1.5625f;

static constexpr int TPB = 256;
static constexpr int VEC = 4;
static constexpr int ITERS = 4;
static constexpr int EPB = TPB * VEC * ITERS;   // 4096
static constexpr int BPR = N / EPB;             // 64

static constexpr int RPB_E = 2;                 // rows per pass_e block
static constexpr int GRID_E = B / RPB_E;        // 32
static constexpr int TPE = 1024;

struct Zeroed {
    unsigned hist[B][NBINS];
    unsigned pos_cnt[B];
    unsigned big_cnt[B];
    double   pos_sum[B];
    double   big_suma[B];
    double   ns, nc;
    unsigned ticket;
};
__device__ Zeroed g_z;         // ~513 KB memset per launch

__device__ __forceinline__ float fsl1(float a) {
    float u = fminf(a, 1.0f);
    return fmaf(u, fmaf(0.5f, u, -1.0f), a);   // exact smooth_l1, branch-free
}
__device__ __forceinline__ float bin_center(int b) {
    return __uint_as_float(CUT_BITS + ((unsigned)b << SHIFT) + (1u << (SHIFT - 1)));
}

// valid in thread 0; internally barriered; all threads must call
__device__ double block_reduce_double(double v) {
    __shared__ double sh[32];
    int lane = threadIdx.x & 31, w = threadIdx.x >> 5;
    #pragma unroll
    for (int o = 16; o; o >>= 1) v += __shfl_down_sync(0xffffffffu, v, o);
    __syncthreads();
    if (lane == 0) sh[w] = v;
    __syncthreads();
    double r = 0.0;
    if (w == 0) {
        int nw = (blockDim.x + 31) >> 5;
        r = (lane < nw) ? sh[lane] : 0.0;
        #pragma unroll
        for (int o = 16; o; o >>= 1) r += __shfl_down_sync(0xffffffffu, r, o);
    }
    __syncthreads();
    return r;
}

// Warp-local suffix select over a 2048-bin hist. All 32 lanes active.
// Returns in every lane: b*, c = count(bins > b*), c < keff <= c + h[b*].
__device__ void warp_select2(const unsigned* h, unsigned keff,
                             int& ob, unsigned& oc) {
    const int lane = threadIdx.x & 31;
    const int chunk = NBINS >> 5;              // 64
    unsigned cs = 0;
    #pragma unroll 8
    for (int j = 0; j < chunk; j++) cs += h[lane * chunk + j];
    unsigned v = cs;
    #pragma unroll
    for (int off = 1; off < 32; off <<= 1) {
        unsigned g = __shfl_down_sync(0xffffffffu, v, off);
        if (lane + off < 32) v += g;
    }
    unsigned vnext = __shfl_down_sync(0xffffffffu, v, 1);
    if (lane == 31) vnext = 0u;
    bool hit = (v >= keff) && (vnext < keff);
    unsigned hb = __ballot_sync(0xffffffffu, hit);
    int c = __ffs(hb) - 1;
    unsigned S = __shfl_sync(0xffffffffu, vnext, c);
    ob = 0; oc = 0;
    #pragma unroll
    for (int g = (chunk >> 5) - 1; g >= 0; g--) {
        unsigned hv = h[c * chunk + g * 32 + lane];
        unsigned w = hv;
        #pragma unroll
        for (int off = 1; off < 32; off <<= 1) {
            unsigned gg = __shfl_down_sync(0xffffffffu, w, off);
            if (lane + off < 32) w += gg;
        }
        unsigned wnext = __shfl_down_sync(0xffffffffu, w, 1);
        if (lane == 31) wnext = 0u;
        unsigned tot = __shfl_sync(0xffffffffu, w, 0);
        bool hit2 = (S + w >= keff) && (S + wnext < keff);
        unsigned hb2 = __ballot_sync(0xffffffffu, hit2);
        if (hb2) {
            int l = __ffs(hb2) - 1;
            unsigned wl = __shfl_sync(0xffffffffu, w, l);
            unsigned hl = __shfl_sync(0xffffffffu, hv, l);
            ob = c * chunk + g * 32 + l;
            oc = S + wl - hl;
            return;
        }
        S += tot;
    }
}

// ---------------- Pass A: data sweep, front-batched loads --------------------
__global__ void __launch_bounds__(TPB, 4) pass_a(const float* __restrict__ yp,
                                                 const float* __restrict__ yt) {
    __shared__ float2 sbuf[TPB][17];            // 16 slots + pad; 34.8 KB
    __shared__ float rs_ps[8], rs_bs[8];
    __shared__ int   rs_pc[8], rs_bc[8];
    const int r = blockIdx.y;
    const int tid = threadIdx.x;
    const unsigned lane = tid & 31u;
    const int w = tid >> 5;
    const size_t base = (size_t)r * N + (size_t)blockIdx.x * EPB;
    int cnt = 0;

    // front-batch ALL loads (8 x LDG.128 in flight -> MLP=8)
    float4 P[ITERS], T[ITERS];
    #pragma unroll
    for (int it = 0; it < ITERS; it++) {
        size_t idx = base + (size_t)it * (TPB * VEC) + (size_t)tid * VEC;
        P[it] = *reinterpret_cast<const float4*>(yp + idx);
        T[it] = *reinterpret_cast<const float4*>(yt + idx);
    }

    // phase 1: filter + stage (1 FFMA + 1 FSETP + predicated STS.64 per elem)
    #pragma unroll
    for (int it = 0; it < ITERS; it++) {
        float pv[4] = {P[it].x, P[it].y, P[it].z, P[it].w};
        float tv[4] = {T[it].x, T[it].y, T[it].z, T[it].w};
        #pragma unroll
        for (int j = 0; j < 4; j++) {
            // t!=0 -> w huge; t==0 -> w=|p|.  interesting <=> w >= CUTF
            float wv = fmaf(fabsf(tv[j]), 1e38f, fabsf(pv[j]));
            if (wv >= CUTF) { sbuf[tid][cnt] = make_float2(pv[j], tv[j]); cnt++; }
        }
    }

    // phase 2: process staged entries (private slots; no sync needed)
    float psum = 0.f, bsum = 0.f; int pc = 0, bc = 0;
    for (int c = 0; c < cnt; c++) {
        float2 e = sbuf[tid][c];
        if (e.y != 0.f) {                        // positive
            psum += fsl1(fabsf(e.x - e.y));
            pc++;
        } else {                                 // big negative (|p| >= 1.5625)
            float a = fabsf(e.x);
            unsigned bin = (__float_as_uint(a) - CUT_BITS) >> SHIFT;
            bin = min(bin, (unsigned)(NBINS - 1));
            atomicAdd(&g_z.hist[r][bin], 1u);    // fire-and-forget RED
            bsum += a; bc++;
        }
    }

    // per-warp shuffle reduce -> smem -> thread 0 -> 4 atomics (1 barrier)
    #pragma unroll
    for (int o = 16; o; o >>= 1) {
        psum += __shfl_down_sync(0xffffffffu, psum, o);
        bsum += __shfl_down_sync(0xffffffffu, bsum, o);
        pc   += __shfl_down_sync(0xffffffffu, pc, o);
        bc   += __shfl_down_sync(0xffffffffu, bc, o);
    }
    if (lane == 0) { rs_ps[w] = psum; rs_bs[w] = bsum; rs_pc[w] = pc; rs_bc[w] = bc; }
    __syncthreads();
    if (tid == 0) {
        double PS = 0.0, BS = 0.0; int PC = 0, BC = 0;
        #pragma unroll
        for (int i = 0; i < 8; i++) {
            PS += (double)rs_ps[i]; BS += (double)rs_bs[i];
            PC += rs_pc[i]; BC += rs_bc[i];
        }
        if (PC) { atomicAdd(&g_z.pos_sum[r], PS); atomicAdd(&g_z.pos_cnt[r], (unsigned)PC); }
        if (BC) { atomicAdd(&g_z.big_suma[r], BS); atomicAdd(&g_z.big_cnt[r], (unsigned)BC); }
    }
}

// ---------------- Pass E: 32 blocks, 2 rows/block, one warp per row ----------
extern __shared__ unsigned dyn_s[];             // RPB_E * NBINS u32 = 16 KB

__global__ void __launch_bounds__(TPE) pass_e(const float* __restrict__ yp,
                                              const float* __restrict__ yt,
                                              float* __restrict__ out) {
    const int tid = threadIdx.x;
    const int row0 = blockIdx.x * RPB_E;
    unsigned (*s_h)[NBINS] = reinterpret_cast<unsigned(*)[NBINS]>(dyn_s);
    __shared__ double s_negr[RPB_E];
    __shared__ double s_kd[RPB_E];
    __shared__ int    s_fb[RPB_E];
    __shared__ int s_b; __shared__ unsigned s_c;
    __shared__ int s_last;

    // cooperative load of 2 row histograms (16 KB): 1 uint4 per thread
    {
        const uint4* src = reinterpret_cast<const uint4*>(&g_z.hist[row0][0]);
        uint4* dst = reinterpret_cast<uint4*>(dyn_s);
        #pragma unroll
        for (int i = 0; i < RPB_E * NBINS / 4 / TPE; i++)
            dst[i * TPE + tid] = src[i * TPE + tid];
    }
    __syncthreads();

    const int w = tid >> 5, lane = tid & 31;
    if (w < RPB_E) {
        const int r = row0 + w;
        const unsigned pcr = g_z.pos_cnt[r];
        const unsigned bcr = g_z.big_cnt[r];
        const double   bsa = g_z.big_suma[r];
        unsigned k = 2u * pcr; if (k > (unsigned)(N - 1)) k = (unsigned)(N - 1);
        const unsigned keff = (k < bcr) ? k : bcr;
        double negr = 0.0;
        if (keff > 0) {
            int b1; unsigned cab;
            warp_select2(s_h[w], keff, b1, cab);
            double acc = 0.0;                   // a-sum over unselected bigs
            for (int b = lane; b < b1; b += 32)
                acc += (double)s_h[w][b] * (double)bin_center(b);
            #pragma unroll
            for (int o = 16; o; o >>= 1) acc += __shfl_down_sync(0xffffffffu, acc, o);
            if (lane == 0) {
                unsigned part_unsel = s_h[w][b1] - (keff - cab);
                acc += (double)part_unsel * (double)bin_center(b1);
                negr = bsa - acc - 0.5 * (double)keff;
            }
        }
        if (lane == 0) { s_negr[w] = negr; s_kd[w] = (double)k; s_fb[w] = (bcr < k); }
    }
    __syncthreads();

    // rare fallback: whole block per flagged row (top k-bc among below-cut negs)
    for (int w2 = 0; w2 < RPB_E; w2++) {
        if (!s_fb[w2]) continue;
        const int r = row0 + w2;
        unsigned* f_h = s_h[0];
        float*    f_f = reinterpret_cast<float*>(s_h[1]);
        for (int i = tid; i < NBINS; i += TPE) { f_h[i] = 0u; f_f[i] = 0.f; }
        __syncthreads();
        const size_t rb = (size_t)r * N;
        for (int i = tid; i < N; i += TPE) {
            float p = yp[rb + i], t = yt[rb + i];
            if (t == 0.f) {
                float a = fabsf(p);
                if (a < CUTF) {
                    unsigned bin = __float_as_uint(a) >> 21;
                    bin = min(bin, (unsigned)(NBINS - 1));
                    atomicAdd(&f_h[bin], 1u);
                    atomicAdd(&f_f[bin], fsl1(a));
                }
            }
        }
        __syncthreads();
        double dt = 0.0;
        for (int i = tid; i < NBINS; i += TPE) dt += (double)f_h[i];
        dt = block_reduce_double(dt);
        if (tid == 0) s_c = (unsigned)(dt + 0.5);
        __syncthreads();
        unsigned tot = s_c;
        unsigned k2 = (unsigned)(s_kd[w2] + 0.5);
        unsigned bcr = g_z.big_cnt[r];
        unsigned kc = k2 - bcr; if (kc > tot) kc = tot;
        __syncthreads();
        if (kc > 0) {
            if (tid < 32) {
                int b1; unsigned cab;
                warp_select2(f_h, kc, b1, cab);
                if (lane == 0) { s_b = b1; s_c = cab; }
            }
            __syncthreads();
            const int b1 = s_b; const unsigned cab = s_c;
            double ext = 0.0;
            for (int b = b1 + 1 + tid; b < NBINS; b += TPE) ext += (double)f_f[b];
            ext = block_reduce_double(ext);
            if (tid == 0) {
                unsigned part = kc - cab;
                if (f_h[b1]) ext += (double)part * ((double)f_f[b1] / (double)f_h[b1]);
                s_negr[w2] += ext;
            }
            __syncthreads();
        }
    }

    if (tid < RPB_E) {
        atomicAdd(&g_z.ns, s_negr[tid]);
        atomicAdd(&g_z.nc, s_kd[tid]);
    }
    __threadfence();
    __syncthreads();
    if (tid == 0)
        s_last = (atomicAdd(&g_z.ticket, 1u) == (unsigned)(GRID_E - 1)) ? 1 : 0;
    __syncthreads();
    if (!s_last) return;

    // ---- final scalar (one block total) ----
    __threadfence();
    double ps  = (tid < B) ? g_z.pos_sum[tid] : 0.0;
    double pcs = (tid < B) ? (double)g_z.pos_cnt[tid] : 0.0;
    ps = block_reduce_double(ps);
    pcs = block_reduce_double(pcs);
    if (tid == 0) {
        double NS = g_z.ns, NC = g_z.nc;
        double pos_loss = (pcs > 0.0) ? ps / pcs : 0.0;
        double neg_loss = (NC > 0.0) ? NS / NC : 0.0;
        out[0] = (float)(2.0 * pos_loss + neg_loss);
    }
}

// ---------------- launch ------------------------------------------------------
extern "C" void kernel_launch(void* const* d_in, const int* in_sizes, int n_in,
                              void* d_out, int out_size) {
    const float* yp = (const float*)d_in[0];
    const float* yt = (const float*)d_in[1];
    float* out = (float*)d_out;

    static bool attr_set = false;
    if (!attr_set) {
        cudaFuncSetAttribute(pass_e, cudaFuncAttributeMaxDynamicSharedMemorySize,
                             RPB_E * NBINS * (int)sizeof(unsigned));
        attr_set = true;
    }

    void* zp = nullptr;
    cudaGetSymbolAddress(&zp, g_z);
    cudaMemsetAsync(zp, 0, sizeof(Zeroed));

    pass_a<<<dim3(BPR, B), TPB>>>(yp, yt);
    pass_e<<<GRID_E, TPE, RPB_E * NBINS * sizeof(unsigned)>>>(yp, yt, out);
}

// round 12
// speedup vs baseline: 1.9408x; 1.2695x over previous
#include <cuda_runtime.h>
#include <cuda_bf16.h>
#include <cstdint>

// OHEM smooth-L1 loss. y_pred,y_true: [64, 262144] fp32 -> scalar fp32.
//  memset : zero scratch (~513 KB).
//  pass_a : sweep (front-batched loads); stage "interesting" (p,t) pairs
//           (pos OR |p|>=1.5625) in private smem slots; phase 2 -> pos stats +
//           2048-bin histogram in SHARED memory + big-neg a-sum; block flushes
//           nonzero bins with coalesced global REDs (~2x fewer L2 atomics).
//  pass_e : 32 blocks x 1024 thr, 2 rows/block, one WARP per row: top-k select
//           + linear neg-sum reconstruction warp-locally over smem histograms.
//           Rare exact fallback. 32-block ticket -> final scalar.

static constexpr int B = 64;
static constexpr int N = 256 * 256 * 4;        // 262144
static constexpr int NBINS = 2048;
static constexpr int SHIFT = 13;               // (key-CUT)>>13 -> 2048 bins, 2 octaves
static constexpr unsigned CUT_BITS = 0x3FC80000u;   // 1.5625f
static constexpr float   CUTF = 1.5625f;

static constexpr int TPB = 256;
static constexpr int VEC = 4;
static constexpr int ITERS = 4;
static constexpr int EPB = TPB * VEC * ITERS;   // 4096
static constexpr int BPR = N / EPB;             // 64

static constexpr int RPB_E = 2;                 // rows per pass_e block
static constexpr int GRID_E = B / RPB_E;        // 32
static constexpr int TPE = 1024;

struct Zeroed {
    unsigned hist[B][NBINS];
    unsigned pos_cnt[B];
    unsigned big_cnt[B];
    double   pos_sum[B];
    double   big_suma[B];
    double   ns, nc;
    unsigned ticket;
};
__device__ Zeroed g_z;         // ~513 KB memset per launch

__device__ __forceinline__ float fsl1(float a) {
    float u = fminf(a, 1.0f);
    return fmaf(u, fmaf(0.5f, u, -1.0f), a);   // exact smooth_l1, branch-free
}
__device__ __forceinline__ float bin_center(int b) {
    return __uint_as_float(CUT_BITS + ((unsigned)b << SHIFT) + (1u << (SHIFT - 1)));
}

// valid in thread 0; internally barriered; all threads must call
__device__ double block_reduce_double(double v) {
    __shared__ double sh[32];
    int lane = threadIdx.x & 31, w = threadIdx.x >> 5;
    #pragma unroll
    for (int o = 16; o; o >>= 1) v += __shfl_down_sync(0xffffffffu, v, o);
    __syncthreads();
    if (lane == 0) sh[w] = v;
    __syncthreads();
    double r = 0.0;
    if (w == 0) {
        int nw = (blockDim.x + 31) >> 5;
        r = (lane < nw) ? sh[lane] : 0.0;
        #pragma unroll
        for (int o = 16; o; o >>= 1) r += __shfl_down_sync(0xffffffffu, r, o);
    }
    __syncthreads();
    return r;
}

// Warp-local suffix select over a 2048-bin hist. All 32 lanes active.
// Returns in every lane: b*, c = count(bins > b*), c < keff <= c + h[b*].
__device__ void warp_select2(const unsigned* h, unsigned keff,
                             int& ob, unsigned& oc) {
    const int lane = threadIdx.x & 31;
    const int chunk = NBINS >> 5;              // 64
    unsigned cs = 0;
    #pragma unroll 8
    for (int j = 0; j < chunk; j++) cs += h[lane * chunk + j];
    unsigned v = cs;
    #pragma unroll
    for (int off = 1; off < 32; off <<= 1) {
        unsigned g = __shfl_down_sync(0xffffffffu, v, off);
        if (lane + off < 32) v += g;
    }
    unsigned vnext = __shfl_down_sync(0xffffffffu, v, 1);
    if (lane == 31) vnext = 0u;
    bool hit = (v >= keff) && (vnext < keff);
    unsigned hb = __ballot_sync(0xffffffffu, hit);
    int c = __ffs(hb) - 1;
    unsigned S = __shfl_sync(0xffffffffu, vnext, c);
    ob = 0; oc = 0;
    #pragma unroll
    for (int g = (chunk >> 5) - 1; g >= 0; g--) {
        unsigned hv = h[c * chunk + g * 32 + lane];
        unsigned w = hv;
        #pragma unroll
        for (int off = 1; off < 32; off <<= 1) {
            unsigned gg = __shfl_down_sync(0xffffffffu, w, off);
            if (lane + off < 32) w += gg;
        }
        unsigned wnext = __shfl_down_sync(0xffffffffu, w, 1);
        if (lane == 31) wnext = 0u;
        unsigned tot = __shfl_sync(0xffffffffu, w, 0);
        bool hit2 = (S + w >= keff) && (S + wnext < keff);
        unsigned hb2 = __ballot_sync(0xffffffffu, hit2);
        if (hb2) {
            int l = __ffs(hb2) - 1;
            unsigned wl = __shfl_sync(0xffffffffu, w, l);
            unsigned hl = __shfl_sync(0xffffffffu, hv, l);
            ob = c * chunk + g * 32 + l;
            oc = S + wl - hl;
            return;
        }
        S += tot;
    }
}

// ---------------- Pass A: sweep with smem hist aggregation -------------------
__global__ void __launch_bounds__(TPB, 4) pass_a(const float* __restrict__ yp,
                                                 const float* __restrict__ yt) {
    __shared__ float2 sbuf[TPB][17];            // 16 slots + pad; 34.8 KB
    __shared__ unsigned s_hist[NBINS];          // 8 KB block-local histogram
    __shared__ float rs_ps[8], rs_bs[8];
    __shared__ int   rs_pc[8], rs_bc[8];
    const int r = blockIdx.y;
    const int tid = threadIdx.x;
    const unsigned lane = tid & 31u;
    const int w = tid >> 5;
    const size_t base = (size_t)r * N + (size_t)blockIdx.x * EPB;
    int cnt = 0;

    #pragma unroll
    for (int i = tid; i < NBINS; i += TPB) s_hist[i] = 0u;

    // front-batch ALL loads (8 x LDG.128 in flight)
    float4 P[ITERS], T[ITERS];
    #pragma unroll
    for (int it = 0; it < ITERS; it++) {
        size_t idx = base + (size_t)it * (TPB * VEC) + (size_t)tid * VEC;
        P[it] = *reinterpret_cast<const float4*>(yp + idx);
        T[it] = *reinterpret_cast<const float4*>(yt + idx);
    }
    __syncthreads();                            // s_hist zero visible

    // phase 1: filter + stage (1 FFMA + 1 FSETP + predicated STS.64 per elem)
    #pragma unroll
    for (int it = 0; it < ITERS; it++) {
        float pv[4] = {P[it].x, P[it].y, P[it].z, P[it].w};
        float tv[4] = {T[it].x, T[it].y, T[it].z, T[it].w};
        #pragma unroll
        for (int j = 0; j < 4; j++) {
            // t!=0 -> w huge; t==0 -> w=|p|.  interesting <=> w >= CUTF
            float wv = fmaf(fabsf(tv[j]), 1e38f, fabsf(pv[j]));
            if (wv >= CUTF) { sbuf[tid][cnt] = make_float2(pv[j], tv[j]); cnt++; }
        }
    }

    // phase 2: process staged entries -> SMEM hist (fast atomics)
    float psum = 0.f, bsum = 0.f; int pc = 0, bc = 0;
    for (int c = 0; c < cnt; c++) {
        float2 e = sbuf[tid][c];
        if (e.y != 0.f) {                        // positive
            psum += fsl1(fabsf(e.x - e.y));
            pc++;
        } else {                                 // big negative (|p| >= 1.5625)
            float a = fabsf(e.x);
            unsigned bin = (__float_as_uint(a) - CUT_BITS) >> SHIFT;
            bin = min(bin, (unsigned)(NBINS - 1));
            atomicAdd(&s_hist[bin], 1u);
            bsum += a; bc++;
        }
    }

    // per-warp shuffle reduce of the 4 scalars
    #pragma unroll
    for (int o = 16; o; o >>= 1) {
        psum += __shfl_down_sync(0xffffffffu, psum, o);
        bsum += __shfl_down_sync(0xffffffffu, bsum, o);
        pc   += __shfl_down_sync(0xffffffffu, pc, o);
        bc   += __shfl_down_sync(0xffffffffu, bc, o);
    }
    if (lane == 0) { rs_ps[w] = psum; rs_bs[w] = bsum; rs_pc[w] = pc; rs_bc[w] = bc; }
    __syncthreads();

    // flush block hist: coalesced, only nonzero bins (~2x fewer global REDs)
    #pragma unroll
    for (int i = tid; i < NBINS; i += TPB) {
        unsigned h = s_hist[i];
        if (h) atomicAdd(&g_z.hist[r][i], h);
    }
    if (tid == 0) {
        double PS = 0.0, BS = 0.0; int PC = 0, BC = 0;
        #pragma unroll
        for (int i = 0; i < 8; i++) {
            PS += (double)rs_ps[i]; BS += (double)rs_bs[i];
            PC += rs_pc[i]; BC += rs_bc[i];
        }
        if (PC) { atomicAdd(&g_z.pos_sum[r], PS); atomicAdd(&g_z.pos_cnt[r], (unsigned)PC); }
        if (BC) { atomicAdd(&g_z.big_suma[r], BS); atomicAdd(&g_z.big_cnt[r], (unsigned)BC); }
    }
}

// ---------------- Pass E: 32 blocks, 2 rows/block, one warp per row ----------
extern __shared__ unsigned dyn_s[];             // RPB_E * NBINS u32 = 16 KB

__global__ void __launch_bounds__(TPE) pass_e(const float* __restrict__ yp,
                                              const float* __restrict__ yt,
                                              float* __restrict__ out) {
    const int tid = threadIdx.x;
    const int row0 = blockIdx.x * RPB_E;
    unsigned (*s_h)[NBINS] = reinterpret_cast<unsigned(*)[NBINS]>(dyn_s);
    __shared__ double s_negr[RPB_E];
    __shared__ double s_kd[RPB_E];
    __shared__ int    s_fb[RPB_E];
    __shared__ int s_b; __shared__ unsigned s_c;
    __shared__ int s_last;

    // cooperative load of 2 row histograms (16 KB): 1 uint4 per thread
    {
        const uint4* src = reinterpret_cast<const uint4*>(&g_z.hist[row0][0]);
        uint4* dst = reinterpret_cast<uint4*>(dyn_s);
        #pragma unroll
        for (int i = 0; i < RPB_E * NBINS / 4 / TPE; i++)
            dst[i * TPE + tid] = src[i * TPE + tid];
    }
    __syncthreads();

    const int w = tid >> 5, lane = tid & 31;
    if (w < RPB_E) {
        const int r = row0 + w;
        const unsigned pcr = g_z.pos_cnt[r];
        const unsigned bcr = g_z.big_cnt[r];
        const double   bsa = g_z.big_suma[r];
        unsigned k = 2u * pcr; if (k > (unsigned)(N - 1)) k = (unsigned)(N - 1);
        const unsigned keff = (k < bcr) ? k : bcr;
        double negr = 0.0;
        if (keff > 0) {
            int b1; unsigned cab;
            warp_select2(s_h[w], keff, b1, cab);
            double acc = 0.0;                   // a-sum over unselected bigs
            for (int b = lane; b < b1; b += 32)
                acc += (double)s_h[w][b] * (double)bin_center(b);
            #pragma unroll
            for (int o = 16; o; o >>= 1) acc += __shfl_down_sync(0xffffffffu, acc, o);
            if (lane == 0) {
                unsigned part_unsel = s_h[w][b1] - (keff - cab);
                acc += (double)part_unsel * (double)bin_center(b1);
                negr = bsa - acc - 0.5 * (double)keff;
            }
        }
        if (lane == 0) { s_negr[w] = negr; s_kd[w] = (double)k; s_fb[w] = (bcr < k); }
    }
    __syncthreads();

    // rare fallback: whole block per flagged row (top k-bc among below-cut negs)
    for (int w2 = 0; w2 < RPB_E; w2++) {
        if (!s_fb[w2]) continue;
        const int r = row0 + w2;
        unsigned* f_h = s_h[0];
        float*    f_f = reinterpret_cast<float*>(s_h[1]);
        for (int i = tid; i < NBINS; i += TPE) { f_h[i] = 0u; f_f[i] = 0.f; }
        __syncthreads();
        const size_t rb = (size_t)r * N;
        for (int i = tid; i < N; i += TPE) {
            float p = yp[rb + i], t = yt[rb + i];
            if (t == 0.f) {
                float a = fabsf(p);
                if (a < CUTF) {
                    unsigned bin = __float_as_uint(a) >> 21;
                    bin = min(bin, (unsigned)(NBINS - 1));
                    atomicAdd(&f_h[bin], 1u);
                    atomicAdd(&f_f[bin], fsl1(a));
                }
            }
        }
        __syncthreads();
        double dt = 0.0;
        for (int i = tid; i < NBINS; i += TPE) dt += (double)f_h[i];
        dt = block_reduce_double(dt);
        if (tid == 0) s_c = (unsigned)(dt + 0.5);
        __syncthreads();
        unsigned tot = s_c;
        unsigned k2 = (unsigned)(s_kd[w2] + 0.5);
        unsigned bcr = g_z.big_cnt[r];
        unsigned kc = k2 - bcr; if (kc > tot) kc = tot;
        __syncthreads();
        if (kc > 0) {
            if (tid < 32) {
                int b1; unsigned cab;
                warp_select2(f_h, kc, b1, cab);
                if (lane == 0) { s_b = b1; s_c = cab; }
            }
            __syncthreads();
            const int b1 = s_b; const unsigned cab = s_c;
            double ext = 0.0;
            for (int b = b1 + 1 + tid; b < NBINS; b += TPE) ext += (double)f_f[b];
            ext = block_reduce_double(ext);
            if (tid == 0) {
                unsigned part = kc - cab;
                if (f_h[b1]) ext += (double)part * ((double)f_f[b1] / (double)f_h[b1]);
                s_negr[w2] += ext;
            }
            __syncthreads();
        }
    }

    if (tid < RPB_E) {
        atomicAdd(&g_z.ns, s_negr[tid]);
        atomicAdd(&g_z.nc, s_kd[tid]);
    }
    __threadfence();
    __syncthreads();
    if (tid == 0)
        s_last = (atomicAdd(&g_z.ticket, 1u) == (unsigned)(GRID_E - 1)) ? 1 : 0;
    __syncthreads();
    if (!s_last) return;

    // ---- final scalar (one block total) ----
    __threadfence();
    double ps  = (tid < B) ? g_z.pos_sum[tid] : 0.0;
    double pcs = (tid < B) ? (double)g_z.pos_cnt[tid] : 0.0;
    ps = block_reduce_double(ps);
    pcs = block_reduce_double(pcs);
    if (tid == 0) {
        double NS = g_z.ns, NC = g_z.nc;
        double pos_loss = (pcs > 0.0) ? ps / pcs : 0.0;
        double neg_loss = (NC > 0.0) ? NS / NC : 0.0;
        out[0] = (float)(2.0 * pos_loss + neg_loss);
    }
}

// ---------------- launch ------------------------------------------------------
extern "C" void kernel_launch(void* const* d_in, const int* in_sizes, int n_in,
                              void* d_out, int out_size) {
    const float* yp = (const float*)d_in[0];
    const float* yt = (const float*)d_in[1];
    float* out = (float*)d_out;

    static bool attr_set = false;
    if (!attr_set) {
        cudaFuncSetAttribute(pass_e, cudaFuncAttributeMaxDynamicSharedMemorySize,
                             RPB_E * NBINS * (int)sizeof(unsigned));
        attr_set = true;
    }

    void* zp = nullptr;
    cudaGetSymbolAddress(&zp, g_z);
    cudaMemsetAsync(zp, 0, sizeof(Zeroed));

    pass_a<<<dim3(BPR, B), TPB>>>(yp, yt);
    pass_e<<<GRID_E, TPE, RPB_E * NBINS * sizeof(unsigned)>>>(yp, yt, out);
}

// round 13
// speedup vs baseline: 1.9618x; 1.0108x over previous
#include <cuda_runtime.h>
#include <cuda_bf16.h>
#include <cstdint>

// OHEM smooth-L1 loss. y_pred,y_true: [64, 262144] fp32 -> scalar fp32.
//  memset : zero scratch (~513 KB).
//  pass_a : sweep, 8192 elem/block in 2 front-batched chunks (__ldcs streaming
//           loads); stage "interesting" (p,t) pairs (pos OR |p|>=1.5625) in
//           private smem slots; phase 2 -> pos stats + 2048-bin SMEM histogram
//           + big-neg a-sum; single coalesced nonzero-bin flush to global REDs.
//  pass_e : 32 blocks x 1024 thr, 2 rows/block, one WARP per row: top-k select
//           + linear neg-sum reconstruction warp-locally over smem histograms
//           (hist stays L2-hot thanks to __ldcs stream). Rare exact fallback.
//           32-block ticket -> final scalar.

static constexpr int B = 64;
static constexpr int N = 256 * 256 * 4;        // 262144
static constexpr int NBINS = 2048;
static constexpr int SHIFT = 13;               // (key-CUT)>>13 -> 2048 bins, 2 octaves
static constexpr unsigned CUT_BITS = 0x3FC80000u;   // 1.5625f
static constexpr float   CUTF = 1.5625f;

static constexpr int TPB = 256;
static constexpr int VEC = 4;
static constexpr int ITERS = 4;                 // per chunk
static constexpr int CHUNKS = 2;
static constexpr int EPB = TPB * VEC * ITERS * CHUNKS;   // 8192
static constexpr int BPR = N / EPB;             // 32

static constexpr int RPB_E = 2;                 // rows per pass_e block
static constexpr int GRID_E = B / RPB_E;        // 32
static constexpr int TPE = 1024;

struct Zeroed {
    unsigned hist[B][NBINS];
    unsigned pos_cnt[B];
    unsigned big_cnt[B];
    double   pos_sum[B];
    double   big_suma[B];
    double   ns, nc;
    unsigned ticket;
};
__device__ Zeroed g_z;         // ~513 KB memset per launch

__device__ __forceinline__ float fsl1(float a) {
    float u = fminf(a, 1.0f);
    return fmaf(u, fmaf(0.5f, u, -1.0f), a);   // exact smooth_l1, branch-free
}
__device__ __forceinline__ float bin_center(int b) {
    return __uint_as_float(CUT_BITS + ((unsigned)b << SHIFT) + (1u << (SHIFT - 1)));
}

// valid in thread 0; internally barriered; all threads must call
__device__ double block_reduce_double(double v) {
    __shared__ double sh[32];
    int lane = threadIdx.x & 31, w = threadIdx.x >> 5;
    #pragma unroll
    for (int o = 16; o; o >>= 1) v += __shfl_down_sync(0xffffffffu, v, o);
    __syncthreads();
    if (lane == 0) sh[w] = v;
    __syncthreads();
    double r = 0.0;
    if (w == 0) {
        int nw = (blockDim.x + 31) >> 5;
        r = (lane < nw) ? sh[lane] : 0.0;
        #pragma unroll
        for (int o = 16; o; o >>= 1) r += __shfl_down_sync(0xffffffffu, r, o);
    }
    __syncthreads();
    return r;
}

// Warp-local suffix select over a 2048-bin hist. All 32 lanes active.
// Returns in every lane: b*, c = count(bins > b*), c < keff <= c + h[b*].
__device__ void warp_select2(const unsigned* h, unsigned keff,
                             int& ob, unsigned& oc) {
    const int lane = threadIdx.x & 31;
    const int chunk = NBINS >> 5;              // 64
    unsigned cs = 0;
    #pragma unroll 8
    for (int j = 0; j < chunk; j++) cs += h[lane * chunk + j];
    unsigned v = cs;
    #pragma unroll
    for (int off = 1; off < 32; off <<= 1) {
        unsigned g = __shfl_down_sync(0xffffffffu, v, off);
        if (lane + off < 32) v += g;
    }
    unsigned vnext = __shfl_down_sync(0xffffffffu, v, 1);
    if (lane == 31) vnext = 0u;
    bool hit = (v >= keff) && (vnext < keff);
    unsigned hb = __ballot_sync(0xffffffffu, hit);
    int c = __ffs(hb) - 1;
    unsigned S = __shfl_sync(0xffffffffu, vnext, c);
    ob = 0; oc = 0;
    #pragma unroll
    for (int g = (chunk >> 5) - 1; g >= 0; g--) {
        unsigned hv = h[c * chunk + g * 32 + lane];
        unsigned w = hv;
        #pragma unroll
        for (int off = 1; off < 32; off <<= 1) {
            unsigned gg = __shfl_down_sync(0xffffffffu, w, off);
            if (lane + off < 32) w += gg;
        }
        unsigned wnext = __shfl_down_sync(0xffffffffu, w, 1);
        if (lane == 31) wnext = 0u;
        unsigned tot = __shfl_sync(0xffffffffu, w, 0);
        bool hit2 = (S + w >= keff) && (S + wnext < keff);
        unsigned hb2 = __ballot_sync(0xffffffffu, hit2);
        if (hb2) {
            int l = __ffs(hb2) - 1;
            unsigned wl = __shfl_sync(0xffffffffu, w, l);
            unsigned hl = __shfl_sync(0xffffffffu, hv, l);
            ob = c * chunk + g * 32 + l;
            oc = S + wl - hl;
            return;
        }
        S += tot;
    }
}

// ---------------- Pass A: chunked sweep with smem hist aggregation -----------
__global__ void __launch_bounds__(TPB, 4) pass_a(const float* __restrict__ yp,
                                                 const float* __restrict__ yt) {
    __shared__ float2 sbuf[TPB][17];            // 16 slots + pad; 34.8 KB
    __shared__ unsigned s_hist[NBINS];          // 8 KB block-local histogram
    __shared__ float rs_ps[8], rs_bs[8];
    __shared__ int   rs_pc[8], rs_bc[8];
    const int r = blockIdx.y;
    const int tid = threadIdx.x;
    const unsigned lane = tid & 31u;
    const int w = tid >> 5;
    const size_t base0 = (size_t)r * N + (size_t)blockIdx.x * EPB;

    #pragma unroll
    for (int i = tid; i < NBINS; i += TPB) s_hist[i] = 0u;
    __syncthreads();

    float psum = 0.f, bsum = 0.f; int pc = 0, bc = 0;

    #pragma unroll
    for (int ch = 0; ch < CHUNKS; ch++) {
        const size_t base = base0 + (size_t)ch * (TPB * VEC * ITERS);

        // front-batch 8 x LDG.128 (streaming / evict-first)
        float4 P[ITERS], T[ITERS];
        #pragma unroll
        for (int it = 0; it < ITERS; it++) {
            size_t idx = base + (size_t)it * (TPB * VEC) + (size_t)tid * VEC;
            P[it] = __ldcs(reinterpret_cast<const float4*>(yp + idx));
            T[it] = __ldcs(reinterpret_cast<const float4*>(yt + idx));
        }

        // filter + stage (1 FFMA + 1 FSETP + predicated STS.64 per elem)
        int cnt = 0;
        #pragma unroll
        for (int it = 0; it < ITERS; it++) {
            float pv[4] = {P[it].x, P[it].y, P[it].z, P[it].w};
            float tv[4] = {T[it].x, T[it].y, T[it].z, T[it].w};
            #pragma unroll
            for (int j = 0; j < 4; j++) {
                // t!=0 -> w huge; t==0 -> w=|p|.  interesting <=> w >= CUTF
                float wv = fmaf(fabsf(tv[j]), 1e38f, fabsf(pv[j]));
                if (wv >= CUTF) { sbuf[tid][cnt] = make_float2(pv[j], tv[j]); cnt++; }
            }
        }

        // process staged entries -> smem hist (fast atomics) + scalars
        for (int c = 0; c < cnt; c++) {
            float2 e = sbuf[tid][c];
            if (e.y != 0.f) {                    // positive
                psum += fsl1(fabsf(e.x - e.y));
                pc++;
            } else {                             // big negative (|p| >= 1.5625)
                float a = fabsf(e.x);
                unsigned bin = (__float_as_uint(a) - CUT_BITS) >> SHIFT;
                bin = min(bin, (unsigned)(NBINS - 1));
                atomicAdd(&s_hist[bin], 1u);
                bsum += a; bc++;
            }
        }
    }

    // per-warp shuffle reduce of the 4 scalars
    #pragma unroll
    for (int o = 16; o; o >>= 1) {
        psum += __shfl_down_sync(0xffffffffu, psum, o);
        bsum += __shfl_down_sync(0xffffffffu, bsum, o);
        pc   += __shfl_down_sync(0xffffffffu, pc, o);
        bc   += __shfl_down_sync(0xffffffffu, bc, o);
    }
    if (lane == 0) { rs_ps[w] = psum; rs_bs[w] = bsum; rs_pc[w] = pc; rs_bc[w] = bc; }
    __syncthreads();

    // flush block hist: coalesced, only nonzero bins
    #pragma unroll
    for (int i = tid; i < NBINS; i += TPB) {
        unsigned h = s_hist[i];
        if (h) atomicAdd(&g_z.hist[r][i], h);
    }
    if (tid == 0) {
        double PS = 0.0, BS = 0.0; int PC = 0, BC = 0;
        #pragma unroll
        for (int i = 0; i < 8; i++) {
            PS += (double)rs_ps[i]; BS += (double)rs_bs[i];
            PC += rs_pc[i]; BC += rs_bc[i];
        }
        if (PC) { atomicAdd(&g_z.pos_sum[r], PS); atomicAdd(&g_z.pos_cnt[r], (unsigned)PC); }
        if (BC) { atomicAdd(&g_z.big_suma[r], BS); atomicAdd(&g_z.big_cnt[r], (unsigned)BC); }
    }
}

// ---------------- Pass E: 32 blocks, 2 rows/block, one warp per row ----------
extern __shared__ unsigned dyn_s[];             // RPB_E * NBINS u32 = 16 KB

__global__ void __launch_bounds__(TPE) pass_e(const float* __restrict__ yp,
                                              const float* __restrict__ yt,
                                              float* __restrict__ out) {
    const int tid = threadIdx.x;
    const int row0 = blockIdx.x * RPB_E;
    unsigned (*s_h)[NBINS] = reinterpret_cast<unsigned(*)[NBINS]>(dyn_s);
    __shared__ double s_negr[RPB_E];
    __shared__ double s_kd[RPB_E];
    __shared__ int    s_fb[RPB_E];
    __shared__ int s_b; __shared__ unsigned s_c;
    __shared__ int s_last;

    // cooperative load of 2 row histograms (16 KB): 1 uint4 per thread
    {
        const uint4* src = reinterpret_cast<const uint4*>(&g_z.hist[row0][0]);
        uint4* dst = reinterpret_cast<uint4*>(dyn_s);
        #pragma unroll
        for (int i = 0; i < RPB_E * NBINS / 4 / TPE; i++)
            dst[i * TPE + tid] = src[i * TPE + tid];
    }
    __syncthreads();

    const int w = tid >> 5, lane = tid & 31;
    if (w < RPB_E) {
        const int r = row0 + w;
        const unsigned pcr = g_z.pos_cnt[r];
        const unsigned bcr = g_z.big_cnt[r];
        const double   bsa = g_z.big_suma[r];
        unsigned k = 2u * pcr; if (k > (unsigned)(N - 1)) k = (unsigned)(N - 1);
        const unsigned keff = (k < bcr) ? k : bcr;
        double negr = 0.0;
        if (keff > 0) {
            int b1; unsigned cab;
            warp_select2(s_h[w], keff, b1, cab);
            double acc = 0.0;                   // a-sum over unselected bigs
            for (int b = lane; b < b1; b += 32)
                acc += (double)s_h[w][b] * (double)bin_center(b);
            #pragma unroll
            for (int o = 16; o; o >>= 1) acc += __shfl_down_sync(0xffffffffu, acc, o);
            if (lane == 0) {
                unsigned part_unsel = s_h[w][b1] - (keff - cab);
                acc += (double)part_unsel * (double)bin_center(b1);
                negr = bsa - acc - 0.5 * (double)keff;
            }
        }
        if (lane == 0) { s_negr[w] = negr; s_kd[w] = (double)k; s_fb[w] = (bcr < k); }
    }
    __syncthreads();

    // rare fallback: whole block per flagged row (top k-bc among below-cut negs)
    for (int w2 = 0; w2 < RPB_E; w2++) {
        if (!s_fb[w2]) continue;
        const int r = row0 + w2;
        unsigned* f_h = s_h[0];
        float*    f_f = reinterpret_cast<float*>(s_h[1]);
        for (int i = tid; i < NBINS; i += TPE) { f_h[i] = 0u; f_f[i] = 0.f; }
        __syncthreads();
        const size_t rb = (size_t)r * N;
        for (int i = tid; i < N; i += TPE) {
            float p = yp[rb + i], t = yt[rb + i];
            if (t == 0.f) {
                float a = fabsf(p);
                if (a < CUTF) {
                    unsigned bin = __float_as_uint(a) >> 21;
                    bin = min(bin, (unsigned)(NBINS - 1));
                    atomicAdd(&f_h[bin], 1u);
                    atomicAdd(&f_f[bin], fsl1(a));
                }
            }
        }
        __syncthreads();
        double dt = 0.0;
        for (int i = tid; i < NBINS; i += TPE) dt += (double)f_h[i];
        dt = block_reduce_double(dt);
        if (tid == 0) s_c = (unsigned)(dt + 0.5);
        __syncthreads();
        unsigned tot = s_c;
        unsigned k2 = (unsigned)(s_kd[w2] + 0.5);
        unsigned bcr = g_z.big_cnt[r];
        unsigned kc = k2 - bcr; if (kc > tot) kc = tot;
        __syncthreads();
        if (kc > 0) {
            if (tid < 32) {
                int b1; unsigned cab;
                warp_select2(f_h, kc, b1, cab);
                if (lane == 0) { s_b = b1; s_c = cab; }
            }
            __syncthreads();
            const int b1 = s_b; const unsigned cab = s_c;
            double ext = 0.0;
            for (int b = b1 + 1 + tid; b < NBINS; b += TPE) ext += (double)f_f[b];
            ext = block_reduce_double(ext);
            if (tid == 0) {
                unsigned part = kc - cab;
                if (f_h[b1]) ext += (double)part * ((double)f_f[b1] / (double)f_h[b1]);
                s_negr[w2] += ext;
            }
            __syncthreads();
        }
    }

    if (tid < RPB_E) {
        atomicAdd(&g_z.ns, s_negr[tid]);
        atomicAdd(&g_z.nc, s_kd[tid]);
    }
    __threadfence();
    __syncthreads();
    if (tid == 0)
        s_last = (atomicAdd(&g_z.ticket, 1u) == (unsigned)(GRID_E - 1)) ? 1 : 0;
    __syncthreads();
    if (!s_last) return;

    // ---- final scalar (one block total) ----
    __threadfence();
    double ps  = (tid < B) ? g_z.pos_sum[tid] : 0.0;
    double pcs = (tid < B) ? (double)g_z.pos_cnt[tid] : 0.0;
    ps = block_reduce_double(ps);
    pcs = block_reduce_double(pcs);
    if (tid == 0) {
        double NS = g_z.ns, NC = g_z.nc;
        double pos_loss = (pcs > 0.0) ? ps / pcs : 0.0;
        double neg_loss = (NC > 0.0) ? NS / NC : 0.0;
        out[0] = (float)(2.0 * pos_loss + neg_loss);
    }
}

// ---------------- launch ------------------------------------------------------
extern "C" void kernel_launch(void* const* d_in, const int* in_sizes, int n_in,
                              void* d_out, int out_size) {
    const float* yp = (const float*)d_in[0];
    const float* yt = (const float*)d_in[1];
    float* out = (float*)d_out;

    static bool attr_set = false;
    if (!attr_set) {
        cudaFuncSetAttribute(pass_e, cudaFuncAttributeMaxDynamicSharedMemorySize,
                             RPB_E * NBINS * (int)sizeof(unsigned));
        attr_set = true;
    }

    void* zp = nullptr;
    cudaGetSymbolAddress(&zp, g_z);
    cudaMemsetAsync(zp, 0, sizeof(Zeroed));

    pass_a<<<dim3(BPR, B), TPB>>>(yp, yt);
    pass_e<<<GRID_E, TPE, RPB_E * NBINS * sizeof(unsigned)>>>(yp, yt, out);
}

// round 14
// speedup vs baseline: 2.0310x; 1.0353x over previous
#include <cuda_runtime.h>
#include <cuda_bf16.h>
#include <cstdint>

// OHEM smooth-L1 loss. y_pred,y_true: [64, 262144] fp32 -> scalar fp32.
//  memset : zero scratch (~513 KB).
//  pass_a : sweep, 8192 elem/block in 2 front-batched chunks (__ldcs streaming
//           loads); stage "interesting" (p,t) pairs (pos OR |p|>=1.5625) in
//           private smem slots; phase 2 -> pos stats + 2048-bin SMEM histogram
//           + big-neg a-sum; single coalesced nonzero-bin flush to global REDs.
//  pass_e : 64 blocks x 128 thr, one block/row. Warp 0 runs the top-k select
//           DIRECTLY on the global histogram (64 LDG/lane -> MLP=64, one DRAM
//           latency) + linear neg-sum reconstruction, all warp-local, zero
//           barriers. Rare exact fallback block-wide. 64-block ticket ->
//           single-warp final scalar.

static constexpr int B = 64;
static constexpr int N = 256 * 256 * 4;        // 262144
static constexpr int NBINS = 2048;
static constexpr int SHIFT = 13;               // (key-CUT)>>13 -> 2048 bins, 2 octaves
static constexpr unsigned CUT_BITS = 0x3FC80000u;   // 1.5625f
static constexpr float   CUTF = 1.5625f;

static constexpr int TPB = 256;
static constexpr int VEC = 4;
static constexpr int ITERS = 4;                 // per chunk
static constexpr int CHUNKS = 2;
static constexpr int EPB = TPB * VEC * ITERS * CHUNKS;   // 8192
static constexpr int BPR = N / EPB;             // 32

static constexpr int TPE = 128;                 // pass_e block (4 warps)

struct Zeroed {
    unsigned hist[B][NBINS];
    unsigned pos_cnt[B];
    unsigned big_cnt[B];
    double   pos_sum[B];
    double   big_suma[B];
    double   ns, nc;
    unsigned ticket;
};
__device__ Zeroed g_z;         // ~513 KB memset per launch

__device__ __forceinline__ float fsl1(float a) {
    float u = fminf(a, 1.0f);
    return fmaf(u, fmaf(0.5f, u, -1.0f), a);   // exact smooth_l1, branch-free
}
__device__ __forceinline__ float bin_center(int b) {
    return __uint_as_float(CUT_BITS + ((unsigned)b << SHIFT) + (1u << (SHIFT - 1)));
}

// Warp-local suffix select over a 2048-bin hist (global or shared pointer).
// All 32 lanes active. Returns in every lane: b*, c = count(bins > b*),
// with c < keff <= c + h[b*].
template <typename LoadFn>
__device__ void warp_select_g(LoadFn ld, unsigned keff, int& ob, unsigned& oc) {
    const int lane = threadIdx.x & 31;
    const int chunk = NBINS >> 5;              // 64
    unsigned cs = 0;
    #pragma unroll
    for (int j = 0; j < chunk; j++) cs += ld(lane * chunk + j);   // 64 indep loads
    unsigned v = cs;
    #pragma unroll
    for (int off = 1; off < 32; off <<= 1) {
        unsigned g = __shfl_down_sync(0xffffffffu, v, off);
        if (lane + off < 32) v += g;
    }
    unsigned vnext = __shfl_down_sync(0xffffffffu, v, 1);
    if (lane == 31) vnext = 0u;
    bool hit = (v >= keff) && (vnext < keff);
    unsigned hb = __ballot_sync(0xffffffffu, hit);
    int c = __ffs(hb) - 1;
    unsigned S = __shfl_sync(0xffffffffu, vnext, c);
    ob = 0; oc = 0;
    #pragma unroll
    for (int g = (chunk >> 5) - 1; g >= 0; g--) {
        unsigned hv = ld(c * chunk + g * 32 + lane);
        unsigned w = hv;
        #pragma unroll
        for (int off = 1; off < 32; off <<= 1) {
            unsigned gg = __shfl_down_sync(0xffffffffu, w, off);
            if (lane + off < 32) w += gg;
        }
        unsigned wnext = __shfl_down_sync(0xffffffffu, w, 1);
        if (lane == 31) wnext = 0u;
        unsigned tot = __shfl_sync(0xffffffffu, w, 0);
        bool hit2 = (S + w >= keff) && (S + wnext < keff);
        unsigned hb2 = __ballot_sync(0xffffffffu, hit2);
        if (hb2) {
            int l = __ffs(hb2) - 1;
            unsigned wl = __shfl_sync(0xffffffffu, w, l);
            unsigned hl = __shfl_sync(0xffffffffu, hv, l);
            ob = c * chunk + g * 32 + l;
            oc = S + wl - hl;
            return;
        }
        S += tot;
    }
}

// ---------------- Pass A: chunked sweep with smem hist aggregation -----------
__global__ void __launch_bounds__(TPB, 4) pass_a(const float* __restrict__ yp,
                                                 const float* __restrict__ yt) {
    __shared__ float2 sbuf[TPB][17];            // 16 slots + pad; 34.8 KB
    __shared__ unsigned s_hist[NBINS];          // 8 KB block-local histogram
    __shared__ float rs_ps[8], rs_bs[8];
    __shared__ int   rs_pc[8], rs_bc[8];
    const int r = blockIdx.y;
    const int tid = threadIdx.x;
    const unsigned lane = tid & 31u;
    const int w = tid >> 5;
    const size_t base0 = (size_t)r * N + (size_t)blockIdx.x * EPB;

    #pragma unroll
    for (int i = tid; i < NBINS; i += TPB) s_hist[i] = 0u;
    __syncthreads();

    float psum = 0.f, bsum = 0.f; int pc = 0, bc = 0;

    #pragma unroll
    for (int ch = 0; ch < CHUNKS; ch++) {
        const size_t base = base0 + (size_t)ch * (TPB * VEC * ITERS);

        // front-batch 8 x LDG.128 (streaming / evict-first)
        float4 P[ITERS], T[ITERS];
        #pragma unroll
        for (int it = 0; it < ITERS; it++) {
            size_t idx = base + (size_t)it * (TPB * VEC) + (size_t)tid * VEC;
            P[it] = __ldcs(reinterpret_cast<const float4*>(yp + idx));
            T[it] = __ldcs(reinterpret_cast<const float4*>(yt + idx));
        }

        // filter + stage (1 FFMA + 1 FSETP + predicated STS.64 per elem)
        int cnt = 0;
        #pragma unroll
        for (int it = 0; it < ITERS; it++) {
            float pv[4] = {P[it].x, P[it].y, P[it].z, P[it].w};
            float tv[4] = {T[it].x, T[it].y, T[it].z, T[it].w};
            #pragma unroll
            for (int j = 0; j < 4; j++) {
                // t!=0 -> w huge; t==0 -> w=|p|.  interesting <=> w >= CUTF
                float wv = fmaf(fabsf(tv[j]), 1e38f, fabsf(pv[j]));
                if (wv >= CUTF) { sbuf[tid][cnt] = make_float2(pv[j], tv[j]); cnt++; }
            }
        }

        // process staged entries -> smem hist (fast atomics) + scalars
        for (int c = 0; c < cnt; c++) {
            float2 e = sbuf[tid][c];
            if (e.y != 0.f) {                    // positive
                psum += fsl1(fabsf(e.x - e.y));
                pc++;
            } else {                             // big negative (|p| >= 1.5625)
                float a = fabsf(e.x);
                unsigned bin = (__float_as_uint(a) - CUT_BITS) >> SHIFT;
                bin = min(bin, (unsigned)(NBINS - 1));
                atomicAdd(&s_hist[bin], 1u);
                bsum += a; bc++;
            }
        }
    }

    // per-warp shuffle reduce of the 4 scalars
    #pragma unroll
    for (int o = 16; o; o >>= 1) {
        psum += __shfl_down_sync(0xffffffffu, psum, o);
        bsum += __shfl_down_sync(0xffffffffu, bsum, o);
        pc   += __shfl_down_sync(0xffffffffu, pc, o);
        bc   += __shfl_down_sync(0xffffffffu, bc, o);
    }
    if (lane == 0) { rs_ps[w] = psum; rs_bs[w] = bsum; rs_pc[w] = pc; rs_bc[w] = bc; }
    __syncthreads();

    // flush block hist: coalesced, only nonzero bins
    #pragma unroll
    for (int i = tid; i < NBINS; i += TPB) {
        unsigned h = s_hist[i];
        if (h) atomicAdd(&g_z.hist[r][i], h);
    }
    if (tid == 0) {
        double PS = 0.0, BS = 0.0; int PC = 0, BC = 0;
        #pragma unroll
        for (int i = 0; i < 8; i++) {
            PS += (double)rs_ps[i]; BS += (double)rs_bs[i];
            PC += rs_pc[i]; BC += rs_bc[i];
        }
        if (PC) { atomicAdd(&g_z.pos_sum[r], PS); atomicAdd(&g_z.pos_cnt[r], (unsigned)PC); }
        if (BC) { atomicAdd(&g_z.big_suma[r], BS); atomicAdd(&g_z.big_cnt[r], (unsigned)BC); }
    }
}

// ---------------- Pass E: one block/row, warp-0 direct-global select ---------
__global__ void __launch_bounds__(TPE) pass_e(const float* __restrict__ yp,
                                              const float* __restrict__ yt,
                                              float* __restrict__ out) {
    const int tid = threadIdx.x;
    const int lane = tid & 31, w = tid >> 5;
    const int r = blockIdx.x;
    __shared__ unsigned f_h[NBINS];             // fallback only
    __shared__ float    f_f[NBINS];             // fallback only
    __shared__ double sh_negr, sh_kd;
    __shared__ int sh_fb, sh_last;
    __shared__ int s_b; __shared__ unsigned s_c;

    const unsigned pcr = g_z.pos_cnt[r];
    const unsigned bcr = g_z.big_cnt[r];
    unsigned k = 2u * pcr; if (k > (unsigned)(N - 1)) k = (unsigned)(N - 1);

    if (w == 0) {
        const double bsa = g_z.big_suma[r];
        const unsigned keff = (k < bcr) ? k : bcr;
        const unsigned* __restrict__ h = g_z.hist[r];
        double negr = 0.0;
        if (keff > 0) {
            int b1; unsigned cab;
            warp_select_g([h](int i) { return __ldg(&h[i]); }, keff, b1, cab);
            double acc = 0.0;                   // a-sum over unselected bigs
            for (int b = lane; b < b1; b += 32)
                acc += (double)__ldg(&h[b]) * (double)bin_center(b);
            #pragma unroll
            for (int o = 16; o; o >>= 1) acc += __shfl_down_sync(0xffffffffu, acc, o);
            if (lane == 0) {
                unsigned part_unsel = __ldg(&h[b1]) - (keff - cab);
                acc += (double)part_unsel * (double)bin_center(b1);
                negr = bsa - acc - 0.5 * (double)keff;
            }
        }
        if (lane == 0) { sh_negr = negr; sh_kd = (double)k; sh_fb = (bcr < k); }
    }
    __syncthreads();

    // rare fallback: block-wide (top k-bc among below-cut negs)
    if (sh_fb) {
        for (int i = tid; i < NBINS; i += TPE) { f_h[i] = 0u; f_f[i] = 0.f; }
        __syncthreads();
        const size_t rb = (size_t)r * N;
        for (int i = tid; i < N; i += TPE) {
            float p = yp[rb + i], t = yt[rb + i];
            if (t == 0.f) {
                float a = fabsf(p);
                if (a < CUTF) {
                    unsigned bin = __float_as_uint(a) >> 21;
                    bin = min(bin, (unsigned)(NBINS - 1));
                    atomicAdd(&f_h[bin], 1u);
                    atomicAdd(&f_f[bin], fsl1(a));
                }
            }
        }
        __syncthreads();
        // block total count
        unsigned tc = 0;
        for (int i = tid; i < NBINS; i += TPE) tc += f_h[i];
        #pragma unroll
        for (int o = 16; o; o >>= 1) tc += __shfl_down_sync(0xffffffffu, tc, o);
        __shared__ unsigned s_tc[4];
        if (lane == 0) s_tc[w] = tc;
        __syncthreads();
        unsigned tot = s_tc[0] + s_tc[1] + s_tc[2] + s_tc[3];
        unsigned kc = k - bcr; if (kc > tot) kc = tot;
        if (kc > 0) {
            if (w == 0) {
                int b1; unsigned cab;
                warp_select_g([](int i) { return f_h[i]; }, kc, b1, cab);
                if (lane == 0) { s_b = b1; s_c = cab; }
            }
            __syncthreads();
            const int b1 = s_b; const unsigned cab = s_c;
            double ext = 0.0;
            for (int b = b1 + 1 + tid; b < NBINS; b += TPE) ext += (double)f_f[b];
            #pragma unroll
            for (int o = 16; o; o >>= 1) ext += __shfl_down_sync(0xffffffffu, ext, o);
            __shared__ double s_ext[4];
            if (lane == 0) s_ext[w] = ext;
            __syncthreads();
            if (tid == 0) {
                double e = s_ext[0] + s_ext[1] + s_ext[2] + s_ext[3];
                unsigned part = kc - cab;
                if (f_h[b1]) e += (double)part * ((double)f_f[b1] / (double)f_h[b1]);
                sh_negr += e;
            }
            __syncthreads();
        }
    }

    if (tid == 0) {
        atomicAdd(&g_z.ns, sh_negr);
        atomicAdd(&g_z.nc, sh_kd);
        __threadfence();
        sh_last = (atomicAdd(&g_z.ticket, 1u) == (unsigned)(B - 1)) ? 1 : 0;
    }
    __syncthreads();
    if (!sh_last) return;

    // ---- final scalar: single warp, 2 rows/lane, shfl double reduce ----
    if (w == 0) {
        __threadfence();
        double ps  = g_z.pos_sum[lane] + g_z.pos_sum[lane + 32];
        double pcs = (double)g_z.pos_cnt[lane] + (double)g_z.pos_cnt[lane + 32];
        #pragma unroll
        for (int o = 16; o; o >>= 1) {
            ps  += __shfl_down_sync(0xffffffffu, ps, o);
            pcs += __shfl_down_sync(0xffffffffu, pcs, o);
        }
        if (lane == 0) {
            double NS = g_z.ns, NC = g_z.nc;
            double pos_loss = (pcs > 0.0) ? ps / pcs : 0.0;
            double neg_loss = (NC > 0.0) ? NS / NC : 0.0;
            out[0] = (float)(2.0 * pos_loss + neg_loss);
        }
    }
}

// ---------------- launch ------------------------------------------------------
extern "C" void kernel_launch(void* const* d_in, const int* in_sizes, int n_in,
                              void* d_out, int out_size) {
    const float* yp = (const float*)d_in[0];
    const float* yt = (const float*)d_in[1];
    float* out = (float*)d_out;

    void* zp = nullptr;
    cudaGetSymbolAddress(&zp, g_z);
    cudaMemsetAsync(zp, 0, sizeof(Zeroed));

    pass_a<<<dim3(BPR, B), TPB>>>(yp, yt);
    pass_e<<<B, TPE>>>(yp, yt, out);
}